// round 1
// baseline (speedup 1.0000x reference)
#include <cuda_runtime.h>

// Loss_57415122813634 — multi-scale shifted-difference loss.
// Inputs (metadata order): PredXYZ [2,3,256,256] f32, GTXYZ [2,3,256,256] f32,
//                          ROIMask [2,1,256,256] f32.
// Output: [loss, NormConst[0], NormConst[1]] (3 floats).

#define HH 256
#define WW 256
#define BB 2
#define LL 3
#define PLANE (HH*WW)
#define NSD 201            // 67 scales * 3 directions
#define DIV1 39518208.0f   // 603 * 65536

// per-batch accumulators: [0]=S1 (|dG|*Rat), [1]=S2 (|dG|*(Rat>0)),
// [2]=pos_cnt (dG>0), [3]=S4 (|dP|), [4]=T1 (|dG - dP/safe_c|), [5]=roi_sum
__device__ double g_acc[BB][6];
__device__ float  g_c[BB];
__device__ float  g_invc[BB];

__device__ __forceinline__ float warpsum(float v) {
#pragma unroll
    for (int o = 16; o; o >>= 1) v += __shfl_xor_sync(0xffffffffu, v, o);
    return v;
}

__global__ void k_zero() {
    int i = threadIdx.x;
    if (i < BB * 6) ((double*)g_acc)[i] = 0.0;
}

__global__ void k_roisum(const float* __restrict__ roi) {
    // grid: 512 blocks x 256 threads; blocks 0..255 -> b=0, 256..511 -> b=1
    int b = blockIdx.x >> 8;
    int idx = ((blockIdx.x & 255) << 8) + threadIdx.x;
    float v = roi[b * PLANE + idx];

    __shared__ float red[8];
    int lane = threadIdx.x & 31, wid = threadIdx.x >> 5;
    float x = warpsum(v);
    if (lane == 0) red[wid] = x;
    __syncthreads();
    if (wid == 0) {
        float y = (lane < 8) ? red[lane] : 0.0f;
        y = warpsum(y);
        if (lane == 0) atomicAdd(&g_acc[b][5], (double)y);
    }
}

// Pass A: accumulate S1, S2, pos_cnt, S4 over the valid region only.
__global__ void __launch_bounds__(256) k_passA(const float* __restrict__ Pred,
                                               const float* __restrict__ GT,
                                               const float* __restrict__ ROI) {
    const int sd    = blockIdx.x;           // 0..200
    const int b     = blockIdx.y;           // 0..1
    const int chunk = blockIdx.z;           // 0..7 (32 rows each)
    const int s   = 1 + 3 * (sd / 3);
    const int dir = sd % 3;                  // 0: (0,s)  1: (s,0)  2: (s,s)
    const int dy  = (dir == 0) ? 0 : s;
    const int dx  = (dir == 1) ? 0 : s;
    const int ymax = HH - dy;
    const int xmax = WW - dx;
    const int y0 = chunk * 32;
    if (y0 >= ymax) return;                  // block-uniform early exit
    const int y1 = min(y0 + 32, ymax);

    const float* Pb = Pred + b * LL * PLANE;
    const float* Gb = GT   + b * LL * PLANE;
    const float* Rb = ROI  + b * PLANE;

    float s1 = 0.f, s2 = 0.f, s3 = 0.f, s4 = 0.f;

    for (int y = y0; y < y1; ++y) {
        const int base0 = y * WW;
        const int base1 = (y + dy) * WW + dx;
        for (int x = threadIdx.x; x < xmax; x += 256) {
            float r = Rb[base0 + x] * Rb[base1 + x];   // 0 or 1
#pragma unroll
            for (int l = 0; l < LL; ++l) {
                const float* P = Pb + l * PLANE;
                const float* G = Gb + l * PLANE;
                float tp = r * (P[base0 + x] - P[base1 + x]);   // difPrd
                float dg = r * (G[base0 + x] - G[base1 + x]);   // difGT
                float d  = dg + 1e-5f;
                float a  = fabsf(dg);
                float q  = __fdividef(tp * a, d);   // |dG| * (dP/d)
                s1 += fmaxf(q, 0.0f);               // |dG| * relu(dP/d)
                s2 += (q  > 0.0f) ? a   : 0.0f;     // |dG| * (Rat>0)
                s3 += (dg > 0.0f) ? 1.f : 0.0f;     // pos count
                s4 += fabsf(tp);                    // |difPrd|
            }
        }
    }

    // block reduction -> double atomics
    __shared__ float red[4][8];
    int lane = threadIdx.x & 31, wid = threadIdx.x >> 5;
    float v[4] = {s1, s2, s3, s4};
#pragma unroll
    for (int i = 0; i < 4; ++i) {
        float x = warpsum(v[i]);
        if (lane == 0) red[i][wid] = x;
    }
    __syncthreads();
    if (wid == 0) {
#pragma unroll
        for (int i = 0; i < 4; ++i) {
            float x = (lane < 8) ? red[i][lane] : 0.0f;
            x = warpsum(x);
            if (lane == 0) atomicAdd(&g_acc[b][i], (double)x);
        }
    }
}

__global__ void k_norm(float* out, int out_size) {
    int b = threadIdx.x;
    if (b < BB) {
        float S1 = (float)g_acc[b][0];
        float S2 = (float)g_acc[b][1];
        float c = S1 / (S2 + 1e-4f);
        g_c[b] = c;
        g_invc[b] = (c > 1e-4f) ? (1.0f / c) : 1.0f;   // 1 / safe_c
        if (out_size >= 3) out[1 + b] = c;
    }
}

// Pass B: T1 = sum |difGT - difPrd/safe_c| = sum roi * |u - t*inv_c|
__global__ void __launch_bounds__(256) k_passB(const float* __restrict__ Pred,
                                               const float* __restrict__ GT,
                                               const float* __restrict__ ROI) {
    const int sd    = blockIdx.x;
    const int b     = blockIdx.y;
    const int chunk = blockIdx.z;
    const int s   = 1 + 3 * (sd / 3);
    const int dir = sd % 3;
    const int dy  = (dir == 0) ? 0 : s;
    const int dx  = (dir == 1) ? 0 : s;
    const int ymax = HH - dy;
    const int xmax = WW - dx;
    const int y0 = chunk * 32;
    if (y0 >= ymax) return;
    const int y1 = min(y0 + 32, ymax);

    const float ic = g_invc[b];
    const float* Pb = Pred + b * LL * PLANE;
    const float* Gb = GT   + b * LL * PLANE;
    const float* Rb = ROI  + b * PLANE;

    float t1 = 0.f;
    for (int y = y0; y < y1; ++y) {
        const int base0 = y * WW;
        const int base1 = (y + dy) * WW + dx;
        for (int x = threadIdx.x; x < xmax; x += 256) {
            float r = Rb[base0 + x] * Rb[base1 + x];
#pragma unroll
            for (int l = 0; l < LL; ++l) {
                const float* P = Pb + l * PLANE;
                const float* G = Gb + l * PLANE;
                float t = P[base0 + x] - P[base1 + x];
                float u = G[base0 + x] - G[base1 + x];
                float e = u - t * ic;
                t1 += r * fabsf(e);
            }
        }
    }

    __shared__ float red[8];
    int lane = threadIdx.x & 31, wid = threadIdx.x >> 5;
    float x = warpsum(t1);
    if (lane == 0) red[wid] = x;
    __syncthreads();
    if (wid == 0) {
        float y = (lane < 8) ? red[lane] : 0.0f;
        y = warpsum(y);
        if (lane == 0) atomicAdd(&g_acc[b][4], (double)y);
    }
}

__global__ void k_final(float* out, int out_size) {
    if (threadIdx.x == 0) {
        float loss = 0.f;
#pragma unroll
        for (int b = 0; b < BB; ++b) {
            float c = g_c[b];
            float term1 = (c > 1e-4f) ? ((float)g_acc[b][4] / DIV1) : 0.0f;
            float roi_sum  = (float)g_acc[b][5];
            float pos      = (float)g_acc[b][2];
            float mean_prd = (float)g_acc[b][3] / pos;
            bool big = roi_sum > 200.0f;
            float term2 = (big && mean_prd > 30.0f && c > 10.0f) ? (mean_prd - 30.0f) : 0.0f;
            float fact = 0.1f / (c + 0.001f);
            float term3 = (big && mean_prd < 2.0f && c < 0.1f) ? ((0.2f - mean_prd) * fact) : 0.0f;
            loss += term1 + term2 + term3;
        }
        out[0] = loss;
    }
}

extern "C" void kernel_launch(void* const* d_in, const int* in_sizes, int n_in,
                              void* d_out, int out_size) {
    const float* Pred = (const float*)d_in[0];
    const float* GT   = (const float*)d_in[1];
    const float* ROI  = (const float*)d_in[2];
    float* out = (float*)d_out;

    k_zero<<<1, 32>>>();
    k_roisum<<<512, 256>>>(ROI);
    k_passA<<<dim3(NSD, BB, 8), 256>>>(Pred, GT, ROI);
    k_norm<<<1, 32>>>(out, out_size);
    k_passB<<<dim3(NSD, BB, 8), 256>>>(Pred, GT, ROI);
    k_final<<<1, 32>>>(out, out_size);
}

// round 2
// speedup vs baseline: 1.3998x; 1.3998x over previous
#include <cuda_runtime.h>

// Loss_57415122813634 — multi-scale shifted-difference loss.
// Inputs: PredXYZ [2,3,256,256] f32, GTXYZ [2,3,256,256] f32, ROIMask [2,1,256,256] f32.
// Output: [loss, NormConst[0], NormConst[1]].

#define HH 256
#define WW 256
#define BB 2
#define LL 3
#define PLANE (HH*WW)
#define NSCALE 67          // s = 1,4,...,199
#define NC 4               // scale chunks per (b,y) for load balance
#define DIV1 39518208.0f   // 603 * 65536

// per-batch accumulators: [0]=S1 (|dG|*Rat), [1]=S2 (|dG|*(Rat>0)),
// [2]=pos_cnt (dG>0), [3]=S4 (|dP|), [4]=T1 (|dG - dP/safe_c|), [5]=roi_sum
__device__ double g_acc[BB][6];
__device__ float  g_c[BB];
__device__ float  g_invc[BB];

__device__ __forceinline__ float warpsum(float v) {
#pragma unroll
    for (int o = 16; o; o >>= 1) v += __shfl_xor_sync(0xffffffffu, v, o);
    return v;
}

__global__ void k_zero() {
    int i = threadIdx.x;
    if (i < BB * 6) ((double*)g_acc)[i] = 0.0;
}

// PASS 0: S1, S2, pos_cnt, S4, roi_sum.  PASS 1: T1.
template<int PASS>
__global__ void __launch_bounds__(256) k_main(const float* __restrict__ Pred,
                                              const float* __restrict__ GT,
                                              const float* __restrict__ ROI) {
    const int y = blockIdx.x;     // base row, ascending => heavy blocks first
    const int c = blockIdx.y;     // scale chunk
    const int b = blockIdx.z;
    const int x = threadIdx.x;

    __shared__ float sP[LL][WW], sG[LL][WW], sR[WW];   // base row y
    __shared__ float tP[LL][WW], tG[LL][WW], tR[WW];   // streamed row y+s

    const float* Pb = Pred + b * LL * PLANE;
    const float* Gb = GT   + b * LL * PLANE;
    const float* Rb = ROI  + b * PLANE;

    // load base row into registers + smem
    float bp[LL], bg[LL];
    const int rowoff = y * WW + x;
    float br = Rb[rowoff];
    sR[x] = br;
#pragma unroll
    for (int l = 0; l < LL; ++l) {
        bp[l] = Pb[l * PLANE + rowoff];
        bg[l] = Gb[l * PLANE + rowoff];
        sP[l][x] = bp[l];
        sG[l][x] = bg[l];
    }
    __syncthreads();

    float a0 = 0.f, a1 = 0.f, a2 = 0.f, a3 = 0.f, a4 = 0.f;
    const float ic = (PASS == 1) ? g_invc[b] : 0.f;

    if (PASS == 0 && c == 0) a4 = br;   // roi row sum (counted once per (b,y))

#define ACCUM(rr, tt, uu)                                        \
    do {                                                         \
        if (PASS == 0) {                                         \
            float tp = (rr) * (tt), dg = (rr) * (uu);            \
            float d = dg + 1e-5f;                                \
            float a = fabsf(dg);                                 \
            float q = __fdividef(tp * a, d);                     \
            a0 += fmaxf(q, 0.0f);                                \
            a1 += (q  > 0.0f) ? a   : 0.0f;                      \
            a2 += (dg > 0.0f) ? 1.f : 0.0f;                      \
            a3 += fabsf(tp);                                     \
        } else {                                                 \
            a0 += (rr) * fabsf((uu) - (tt) * ic);                \
        }                                                        \
    } while (0)

    // ---- horizontal direction (0, s): entirely from cached base row ----
    for (int k = c; k < NSCALE; k += NC) {
        const int s = 1 + 3 * k;
        if (x < WW - s) {
            float r = br * sR[x + s];
#pragma unroll
            for (int l = 0; l < LL; ++l) {
                float t = bp[l] - sP[l][x + s];
                float u = bg[l] - sG[l][x + s];
                ACCUM(r, t, u);
            }
        }
    }

    // ---- vertical (s,0) + diagonal (s,s): stream row y+s once per scale ----
    for (int k = c; k < NSCALE; k += NC) {
        const int s = 1 + 3 * k;
        if (y + s >= HH) break;                 // uniform across block
        __syncthreads();                        // protect t-arrays
        const int soff = (y + s) * WW + x;
        float vr = Rb[soff];
        tR[x] = vr;
        float vp[LL], vg[LL];
#pragma unroll
        for (int l = 0; l < LL; ++l) {
            vp[l] = Pb[l * PLANE + soff];
            vg[l] = Gb[l * PLANE + soff];
            tP[l][x] = vp[l];
            tG[l][x] = vg[l];
        }
        __syncthreads();

        // vertical: both operands in registers
        {
            float r = br * vr;
#pragma unroll
            for (int l = 0; l < LL; ++l) {
                float t = bp[l] - vp[l];
                float u = bg[l] - vg[l];
                ACCUM(r, t, u);
            }
        }
        // diagonal: shifted access into streamed row via smem
        if (x < WW - s) {
            float r = br * tR[x + s];
#pragma unroll
            for (int l = 0; l < LL; ++l) {
                float t = bp[l] - tP[l][x + s];
                float u = bg[l] - tG[l][x + s];
                ACCUM(r, t, u);
            }
        }
    }
#undef ACCUM

    // ---- block reduction -> double atomics ----
    __shared__ float red[8];
    const int lane = threadIdx.x & 31, wid = threadIdx.x >> 5;
    const int nsum = (PASS == 0) ? 5 : 1;
    float vals[5] = {a0, a1, a2, a3, a4};
    const int slot[5] = {(PASS == 0) ? 0 : 4, 1, 2, 3, 5};
#pragma unroll
    for (int i = 0; i < 5; ++i) {
        if (i >= nsum) break;
        float v = warpsum(vals[i]);
        __syncthreads();
        if (lane == 0) red[wid] = v;
        __syncthreads();
        if (wid == 0) {
            float w = (lane < 8) ? red[lane] : 0.0f;
            w = warpsum(w);
            if (lane == 0 && w != 0.0f) atomicAdd(&g_acc[b][slot[i]], (double)w);
        }
    }
}

__global__ void k_norm(float* out, int out_size) {
    int b = threadIdx.x;
    if (b < BB) {
        float S1 = (float)g_acc[b][0];
        float S2 = (float)g_acc[b][1];
        float c = S1 / (S2 + 1e-4f);
        g_c[b] = c;
        g_invc[b] = (c > 1e-4f) ? (1.0f / c) : 1.0f;   // 1/safe_c
        if (out_size >= 3) out[1 + b] = c;
    }
}

__global__ void k_final(float* out, int out_size) {
    if (threadIdx.x == 0) {
        float loss = 0.f;
#pragma unroll
        for (int b = 0; b < BB; ++b) {
            float c = g_c[b];
            float term1 = (c > 1e-4f) ? ((float)g_acc[b][4] / DIV1) : 0.0f;
            float roi_sum  = (float)g_acc[b][5];
            float pos      = (float)g_acc[b][2];
            float mean_prd = (float)g_acc[b][3] / pos;
            bool big = roi_sum > 200.0f;
            float term2 = (big && mean_prd > 30.0f && c > 10.0f) ? (mean_prd - 30.0f) : 0.0f;
            float fact = 0.1f / (c + 0.001f);
            float term3 = (big && mean_prd < 2.0f && c < 0.1f) ? ((0.2f - mean_prd) * fact) : 0.0f;
            loss += term1 + term2 + term3;
        }
        out[0] = loss;
    }
}

extern "C" void kernel_launch(void* const* d_in, const int* in_sizes, int n_in,
                              void* d_out, int out_size) {
    const float* Pred = (const float*)d_in[0];
    const float* GT   = (const float*)d_in[1];
    const float* ROI  = (const float*)d_in[2];
    float* out = (float*)d_out;

    dim3 grid(HH, NC, BB);
    k_zero<<<1, 32>>>();
    k_main<0><<<grid, 256>>>(Pred, GT, ROI);
    k_norm<<<1, 32>>>(out, out_size);
    k_main<1><<<grid, 256>>>(Pred, GT, ROI);
    k_final<<<1, 32>>>(out, out_size);
}

// round 3
// speedup vs baseline: 1.5996x; 1.1427x over previous
#include <cuda_runtime.h>

// Loss_57415122813634 — multi-scale shifted-difference loss.
// Inputs: PredXYZ [2,3,256,256] f32, GTXYZ [2,3,256,256] f32, ROIMask [2,1,256,256] f32.
// Output: [loss, NormConst[0], NormConst[1]].

#define HH 256
#define WW 256
#define BB 2
#define LL 3
#define PLANE (HH*WW)
#define NSCALE 67          // s = 1,4,...,199
#define NC 8               // streamed-row chunks for VD blocks
#define MROWS 4            // base rows per VD block (stride 3)
#define NGRP 66            // 22 * 3 row-groups
#define VDN (NGRP*NC*BB)   // 1056 VD blocks
#define HN  (HH*BB)        // 512 H blocks
#define DIV1 39518208.0f   // 603 * 65536

// per-batch accumulators: [0]=S1 (|dG|*Rat), [1]=S2 (|dG|*(Rat>0)),
// [2]=pos_cnt, [3]=S4 (|dP|), [4]=T1, [5]=roi_sum
__device__ double g_acc[BB][6];

__device__ __forceinline__ float warpsum(float v) {
#pragma unroll
    for (int o = 16; o; o >>= 1) v += __shfl_xor_sync(0xffffffffu, v, o);
    return v;
}

template<int PASS>
__global__ void __launch_bounds__(256) k_main(const float* __restrict__ Pred,
                                              const float* __restrict__ GT,
                                              const float* __restrict__ ROI) {
    const int x  = threadIdx.x;
    const int id = blockIdx.x;

    __shared__ float4 s4[2][WW];   // {P0,P1,P2,G0}
    __shared__ float2 s2[2][WW];   // {G1,G2}
    __shared__ float  sr[2][WW];   // roi

    float a0 = 0.f, a1 = 0.f, a2 = 0.f, a3 = 0.f, a4 = 0.f;
    int b;

#define ACCUM(rr, tt, uu)                                        \
    do {                                                         \
        if (PASS == 0) {                                         \
            float tp = (rr) * (tt), dg = (rr) * (uu);            \
            float d = dg + 1e-5f;                                \
            float a = fabsf(dg);                                 \
            float q = __fdividef(tp * a, d);                     \
            a0 += fmaxf(q, 0.0f);                                \
            a1 += (q  > 0.0f) ? a   : 0.0f;                      \
            a2 += (dg > 0.0f) ? 1.f : 0.0f;                      \
            a3 += fabsf(tp);                                     \
        } else {                                                 \
            a0 = fmaf((rr), fabsf((uu) - (tt) * ic), a0);        \
        }                                                        \
    } while (0)

    if (id < VDN) {
        // ------- VD role: 4 base rows (stride 3), stream rows y0+1+3j -------
        const int cpos = id % NC;
        const int g    = (id / NC) % NGRP;
        b              = id / (NC * NGRP);
        const int y0   = 12 * (g / 3) + (g % 3);

        const float* Pb = Pred + b * LL * PLANE;
        const float* Gb = GT   + b * LL * PLANE;
        const float* Rb = ROI  + b * PLANE;

        float ic = 0.f;
        if (PASS == 1) {
            float S1 = (float)g_acc[b][0], S2 = (float)g_acc[b][1];
            float c = S1 / (S2 + 1e-4f);
            ic = (c > 1e-4f) ? (1.0f / c) : 1.0f;
        }

        float bp[MROWS][LL], bg[MROWS][LL], br[MROWS];
#pragma unroll
        for (int i = 0; i < MROWS; ++i) {
            int yr = y0 + 3 * i;
            int off = min(yr, HH - 1) * WW + x;
            br[i] = (yr < HH) ? Rb[off] : 0.0f;
#pragma unroll
            for (int l = 0; l < LL; ++l) {
                bp[i][l] = Pb[l * PLANE + off];
                bg[i][l] = Gb[l * PLANE + off];
            }
        }

        const int jmax = min((HH - 2 - y0) / 3, NSCALE + MROWS - 2);  // pairs need j-i<=66
        int p = 0;
        for (int j = cpos; j <= jmax; j += NC) {
            const int Roff = (y0 + 1 + 3 * j) * WW + x;
            float vr  = Rb[Roff];
            float vp0 = Pb[Roff], vp1 = Pb[PLANE + Roff], vp2 = Pb[2 * PLANE + Roff];
            float vg0 = Gb[Roff], vg1 = Gb[PLANE + Roff], vg2 = Gb[2 * PLANE + Roff];
            s4[p][x] = make_float4(vp0, vp1, vp2, vg0);
            s2[p][x] = make_float2(vg1, vg2);
            sr[p][x] = vr;
            __syncthreads();
#pragma unroll
            for (int i = 0; i < MROWS; ++i) {
                if (i <= j && j - i < NSCALE) {
                    // vertical: all registers
                    float rv = br[i] * vr;
                    ACCUM(rv, bp[i][0] - vp0, bg[i][0] - vg0);
                    ACCUM(rv, bp[i][1] - vp1, bg[i][1] - vg1);
                    ACCUM(rv, bp[i][2] - vp2, bg[i][2] - vg2);
                    // diagonal: packed smem at x+s
                    int xs = x + 3 * (j - i) + 1;
                    if (xs < WW) {
                        float4 A  = s4[p][xs];
                        float2 B2 = s2[p][xs];
                        float rd  = br[i] * sr[p][xs];
                        ACCUM(rd, bp[i][0] - A.x, bg[i][0] - A.w);
                        ACCUM(rd, bp[i][1] - A.y, bg[i][1] - B2.x);
                        ACCUM(rd, bp[i][2] - A.z, bg[i][2] - B2.y);
                    }
                }
            }
            p ^= 1;
        }
    } else {
        // ------- H role: one base row, all 67 horizontal scales -------
        const int hid = id - VDN;
        b = hid & 1;
        const int y = hid >> 1;

        const float* Pb = Pred + b * LL * PLANE;
        const float* Gb = GT   + b * LL * PLANE;
        const float* Rb = ROI  + b * PLANE;

        float ic = 0.f;
        if (PASS == 1) {
            float S1 = (float)g_acc[b][0], S2 = (float)g_acc[b][1];
            float c = S1 / (S2 + 1e-4f);
            ic = (c > 1e-4f) ? (1.0f / c) : 1.0f;
        }

        const int off = y * WW + x;
        float br0 = Rb[off];
        float hp[LL], hg[LL];
#pragma unroll
        for (int l = 0; l < LL; ++l) {
            hp[l] = Pb[l * PLANE + off];
            hg[l] = Gb[l * PLANE + off];
        }
        s4[0][x] = make_float4(hp[0], hp[1], hp[2], hg[0]);
        s2[0][x] = make_float2(hg[1], hg[2]);
        sr[0][x] = br0;
        if (PASS == 0) a4 = br0;     // roi_sum, counted once per (b,y)
        __syncthreads();

        for (int k = 0; k < NSCALE; ++k) {
            int xs = x + 1 + 3 * k;
            if (xs < WW) {
                float4 A  = s4[0][xs];
                float2 B2 = s2[0][xs];
                float rr  = br0 * sr[0][xs];
                ACCUM(rr, hp[0] - A.x, hg[0] - A.w);
                ACCUM(rr, hp[1] - A.y, hg[1] - B2.x);
                ACCUM(rr, hp[2] - A.z, hg[2] - B2.y);
            }
        }
    }
#undef ACCUM

    // ------- block reduction -> double atomics -------
    __shared__ float red[8];
    const int lane = threadIdx.x & 31, wid = threadIdx.x >> 5;
    const int nsum = (PASS == 0) ? 5 : 1;
    float vals[5] = {a0, a1, a2, a3, a4};
    const int slot[5] = {(PASS == 0) ? 0 : 4, 1, 2, 3, 5};
#pragma unroll
    for (int i = 0; i < 5; ++i) {
        if (i >= nsum) break;
        float v = warpsum(vals[i]);
        __syncthreads();
        if (lane == 0) red[wid] = v;
        __syncthreads();
        if (wid == 0) {
            float w = (lane < 8) ? red[lane] : 0.0f;
            w = warpsum(w);
            if (lane == 0 && w != 0.0f) atomicAdd(&g_acc[b][slot[i]], (double)w);
        }
    }
}

__global__ void k_final(float* out, int out_size) {
    if (threadIdx.x == 0) {
        float loss = 0.f;
        float cs[BB];
#pragma unroll
        for (int b = 0; b < BB; ++b) {
            float S1 = (float)g_acc[b][0], S2 = (float)g_acc[b][1];
            float c = S1 / (S2 + 1e-4f);
            cs[b] = c;
            float term1 = (c > 1e-4f) ? ((float)g_acc[b][4] / DIV1) : 0.0f;
            float roi_sum  = (float)g_acc[b][5];
            float pos      = (float)g_acc[b][2];
            float mean_prd = (float)g_acc[b][3] / pos;
            bool big = roi_sum > 200.0f;
            float term2 = (big && mean_prd > 30.0f && c > 10.0f) ? (mean_prd - 30.0f) : 0.0f;
            float fact = 0.1f / (c + 0.001f);
            float term3 = (big && mean_prd < 2.0f && c < 0.1f) ? ((0.2f - mean_prd) * fact) : 0.0f;
            loss += term1 + term2 + term3;
        }
        if (out_size >= 1) out[0] = loss;
        if (out_size >= 3) { out[1] = cs[0]; out[2] = cs[1]; }
        // reset accumulators for the next graph replay (statics start zeroed)
#pragma unroll
        for (int i = 0; i < BB * 6; ++i) ((double*)g_acc)[i] = 0.0;
    }
}

extern "C" void kernel_launch(void* const* d_in, const int* in_sizes, int n_in,
                              void* d_out, int out_size) {
    const float* Pred = (const float*)d_in[0];
    const float* GT   = (const float*)d_in[1];
    const float* ROI  = (const float*)d_in[2];
    float* out = (float*)d_out;

    const int TOT = VDN + HN;   // 1568 blocks
    k_main<0><<<TOT, 256>>>(Pred, GT, ROI);
    k_main<1><<<TOT, 256>>>(Pred, GT, ROI);
    k_final<<<1, 32>>>(out, out_size);
}

// round 4
// speedup vs baseline: 1.6317x; 1.0201x over previous
#include <cuda_runtime.h>

// Loss_57415122813634 — multi-scale shifted-difference loss (fused persistent kernel).
// Inputs: PredXYZ [2,3,256,256] f32, GTXYZ [2,3,256,256] f32, ROIMask [2,1,256,256] f32.
// Output: [loss, NormConst[0], NormConst[1]].

#define HH 256
#define WW 256
#define BB 2
#define LL 3
#define PLANE (HH*WW)
#define NSCALE 67          // s = 1,4,...,199
#define NC 8               // streamed-row chunks for VD items
#define MROWS 4            // base rows per VD item (stride 3)
#define NGRP 66            // 22 * 3 row-groups
#define VDN (NGRP*NC*BB)   // 1056 VD items
#define HN  (HH*BB)        // 512 H items
#define TOT (VDN+HN)       // 1568 work items
#define GRID 592           // 4 blocks/SM * 148 SMs, all co-resident
#define DIV1 39518208.0f   // 603 * 65536

// per-batch accumulators: [0]=S1 (|dG|*Rat), [1]=S2 (|dG|*(Rat>0)),
// [2]=pos_cnt, [3]=S4 (|dP|), [4]=T1, [5]=roi_sum
__device__ double g_acc[BB][6];
__device__ unsigned bar_ctr;             // zero-init
__device__ volatile unsigned bar_gen;    // zero-init

struct Smem {
    float4 s4[2][WW];   // {P0,P1,P2,G0}
    float2 s2[2][WW];   // {G1,G2}
    float  sr[2][WW];   // roi
    float  red[8];
};

__device__ __forceinline__ float warpsum(float v) {
#pragma unroll
    for (int o = 16; o; o >>= 1) v += __shfl_xor_sync(0xffffffffu, v, o);
    return v;
}

__device__ __forceinline__ void grid_barrier() {
    __syncthreads();
    if (threadIdx.x == 0) {
        __threadfence();
        unsigned gen = bar_gen;
        if (atomicAdd(&bar_ctr, 1) == GRID - 1) {
            bar_ctr = 0;
            __threadfence();
            bar_gen = gen + 1;
        } else {
            while (bar_gen == gen) __nanosleep(64);
        }
        __threadfence();
    }
    __syncthreads();
}

// PASS 0 accumulators: a0=S1, a1=S2, a2=pos, a3=S4, a4=roi_sum. PASS 1: a0=T1.
template<int PASS>
__device__ __forceinline__ void do_item(int id,
                                        const float* __restrict__ Pred,
                                        const float* __restrict__ GT,
                                        const float* __restrict__ ROI,
                                        Smem* sm, float ic0, float ic1) {
    const int x = threadIdx.x;
    float a0 = 0.f, a1 = 0.f, a2 = 0.f, a3 = 0.f, a4 = 0.f;
    int b;

    // P: bool (roi pair active). t: pred diff. u: gt diff. unmasked math,
    // predicated accumulation (exact: roi in {0,1}).
#define ACCUM(PP, tt, uu)                                         \
    do {                                                          \
        if (PASS == 0) {                                          \
            float t_ = (tt), u_ = (uu);                           \
            float q = __fdividef(t_ * fabsf(u_), u_ + 1e-5f);     \
            if ((PP) && q  > 0.0f) { a0 += q; a1 += fabsf(u_); }  \
            if ((PP) && u_ > 0.0f) a2 += 1.0f;                    \
            if (PP) a3 += fabsf(t_);                              \
        } else {                                                  \
            float e = (uu) - (tt) * ic;                           \
            if (PP) a0 += fabsf(e);                               \
        }                                                         \
    } while (0)

    if (id < VDN) {
        // ---- VD item: 4 base rows (stride 3), stream rows y0+1+3j ----
        const int cpos = id % NC;
        const int g    = (id / NC) % NGRP;
        b              = id / (NC * NGRP);
        const int y0   = 12 * (g / 3) + (g % 3);
        const float ic = (PASS == 1) ? (b ? ic1 : ic0) : 0.f;

        const float* Pb = Pred + b * LL * PLANE;
        const float* Gb = GT   + b * LL * PLANE;
        const float* Rb = ROI  + b * PLANE;

        float bp[MROWS][LL], bg[MROWS][LL];
        bool  Pbase[MROWS];
#pragma unroll
        for (int i = 0; i < MROWS; ++i) {
            int yr = y0 + 3 * i;
            int off = min(yr, HH - 1) * WW + x;
            Pbase[i] = (yr < HH) && (Rb[off] > 0.0f);
#pragma unroll
            for (int l = 0; l < LL; ++l) {
                bp[i][l] = Pb[l * PLANE + off];
                bg[i][l] = Gb[l * PLANE + off];
            }
        }

        const int jmax = min((HH - 2 - y0) / 3, NSCALE + MROWS - 2);
        int p = 0;
        for (int j = cpos; j <= jmax; j += NC) {
            const int Roff = (y0 + 1 + 3 * j) * WW + x;
            float vr  = Rb[Roff];
            float vp0 = Pb[Roff], vp1 = Pb[PLANE + Roff], vp2 = Pb[2 * PLANE + Roff];
            float vg0 = Gb[Roff], vg1 = Gb[PLANE + Roff], vg2 = Gb[2 * PLANE + Roff];
            sm->s4[p][x] = make_float4(vp0, vp1, vp2, vg0);
            sm->s2[p][x] = make_float2(vg1, vg2);
            sm->sr[p][x] = vr;
            __syncthreads();
            const bool Pv = vr > 0.0f;
#pragma unroll
            for (int i = 0; i < MROWS; ++i) {
                if (i <= j && j - i < NSCALE) {
                    // vertical: all registers
                    bool PV = Pbase[i] && Pv;
                    ACCUM(PV, bp[i][0] - vp0, bg[i][0] - vg0);
                    ACCUM(PV, bp[i][1] - vp1, bg[i][1] - vg1);
                    ACCUM(PV, bp[i][2] - vp2, bg[i][2] - vg2);
                    // diagonal: packed smem at x+s
                    int xs = x + 3 * (j - i) + 1;
                    if (xs < WW) {
                        float4 A  = sm->s4[p][xs];
                        float2 B2 = sm->s2[p][xs];
                        bool PD = Pbase[i] && (sm->sr[p][xs] > 0.0f);
                        ACCUM(PD, bp[i][0] - A.x, bg[i][0] - A.w);
                        ACCUM(PD, bp[i][1] - A.y, bg[i][1] - B2.x);
                        ACCUM(PD, bp[i][2] - A.z, bg[i][2] - B2.y);
                    }
                }
            }
            p ^= 1;
        }
    } else {
        // ---- H item: one base row, all 67 horizontal scales ----
        const int hid = id - VDN;
        b = hid & 1;
        const int y = hid >> 1;
        const float ic = (PASS == 1) ? (b ? ic1 : ic0) : 0.f;

        const float* Pb = Pred + b * LL * PLANE;
        const float* Gb = GT   + b * LL * PLANE;
        const float* Rb = ROI  + b * PLANE;

        const int off = y * WW + x;
        float br0 = Rb[off];
        const bool Pb0 = br0 > 0.0f;
        float hp[LL], hg[LL];
#pragma unroll
        for (int l = 0; l < LL; ++l) {
            hp[l] = Pb[l * PLANE + off];
            hg[l] = Gb[l * PLANE + off];
        }
        sm->s4[0][x] = make_float4(hp[0], hp[1], hp[2], hg[0]);
        sm->s2[0][x] = make_float2(hg[1], hg[2]);
        sm->sr[0][x] = br0;
        if (PASS == 0) a4 = br0;     // roi_sum, once per (b,y)
        __syncthreads();

        for (int k = 0; k < NSCALE; ++k) {
            int xs = x + 1 + 3 * k;
            if (xs < WW) {
                float4 A  = sm->s4[0][xs];
                float2 B2 = sm->s2[0][xs];
                bool PH = Pb0 && (sm->sr[0][xs] > 0.0f);
                ACCUM(PH, hp[0] - A.x, hg[0] - A.w);
                ACCUM(PH, hp[1] - A.y, hg[1] - B2.x);
                ACCUM(PH, hp[2] - A.z, hg[2] - B2.y);
            }
        }
    }
#undef ACCUM

    // ---- block reduction -> double atomics ----
    const int lane = threadIdx.x & 31, wid = threadIdx.x >> 5;
    const int nsum = (PASS == 0) ? 5 : 1;
    float vals[5] = {a0, a1, a2, a3, a4};
    const int slot[5] = {(PASS == 0) ? 0 : 4, 1, 2, 3, 5};
#pragma unroll
    for (int i = 0; i < 5; ++i) {
        if (i >= nsum) break;
        float v = warpsum(vals[i]);
        __syncthreads();
        if (lane == 0) sm->red[wid] = v;
        __syncthreads();
        if (wid == 0) {
            float w = (lane < 8) ? sm->red[lane] : 0.0f;
            w = warpsum(w);
            if (lane == 0 && w != 0.0f) atomicAdd(&g_acc[b][slot[i]], (double)w);
        }
    }
    __syncthreads();   // smem safe for next item
}

__global__ void __launch_bounds__(256, 4)
k_fused(const float* __restrict__ Pred, const float* __restrict__ GT,
        const float* __restrict__ ROI, float* out, int out_size) {
    __shared__ Smem sm;

    // ---- pass 0 ----
    for (int it = blockIdx.x; it < TOT; it += GRID)
        do_item<0>(it, Pred, GT, ROI, &sm, 0.f, 0.f);

    grid_barrier();

    // ---- NormConst (every thread, from 4 global doubles) ----
    float ic[BB];
#pragma unroll
    for (int bb = 0; bb < BB; ++bb) {
        float S1 = (float)g_acc[bb][0], S2 = (float)g_acc[bb][1];
        float c = S1 / (S2 + 1e-4f);
        ic[bb] = (c > 1e-4f) ? (1.0f / c) : 1.0f;
    }

    // ---- pass 1 ----
    for (int it = blockIdx.x; it < TOT; it += GRID)
        do_item<1>(it, Pred, GT, ROI, &sm, ic[0], ic[1]);

    grid_barrier();

    // ---- finalize (block 0) ----
    if (blockIdx.x == 0 && threadIdx.x == 0) {
        float loss = 0.f;
        float cs[BB];
#pragma unroll
        for (int bb = 0; bb < BB; ++bb) {
            float S1 = (float)g_acc[bb][0], S2 = (float)g_acc[bb][1];
            float c = S1 / (S2 + 1e-4f);
            cs[bb] = c;
            float term1 = (c > 1e-4f) ? ((float)g_acc[bb][4] / DIV1) : 0.0f;
            float roi_sum  = (float)g_acc[bb][5];
            float pos      = (float)g_acc[bb][2];
            float mean_prd = (float)g_acc[bb][3] / pos;
            bool big = roi_sum > 200.0f;
            float term2 = (big && mean_prd > 30.0f && c > 10.0f) ? (mean_prd - 30.0f) : 0.0f;
            float fact = 0.1f / (c + 0.001f);
            float term3 = (big && mean_prd < 2.0f && c < 0.1f) ? ((0.2f - mean_prd) * fact) : 0.0f;
            loss += term1 + term2 + term3;
        }
        if (out_size >= 1) out[0] = loss;
        if (out_size >= 3) { out[1] = cs[0]; out[2] = cs[1]; }
        // reset accumulators for the next graph replay (statics start zeroed)
#pragma unroll
        for (int i = 0; i < BB * 6; ++i) ((double*)g_acc)[i] = 0.0;
    }
}

extern "C" void kernel_launch(void* const* d_in, const int* in_sizes, int n_in,
                              void* d_out, int out_size) {
    const float* Pred = (const float*)d_in[0];
    const float* GT   = (const float*)d_in[1];
    const float* ROI  = (const float*)d_in[2];
    float* out = (float*)d_out;

    k_fused<<<GRID, 256>>>(Pred, GT, ROI, out, out_size);
}

// round 5
// speedup vs baseline: 1.6414x; 1.0060x over previous
#include <cuda_runtime.h>

// Loss_57415122813634 — multi-scale shifted-difference loss (fused persistent
// kernel with dynamic work-stealing).
// Inputs: PredXYZ [2,3,256,256] f32, GTXYZ [2,3,256,256] f32, ROIMask [2,1,256,256] f32.
// Output: [loss, NormConst[0], NormConst[1]].

#define HH 256
#define WW 256
#define BB 2
#define LL 3
#define PLANE (HH*WW)
#define NSCALE 67          // s = 1,4,...,199
#define NC 8               // streamed-row chunks for VD items
#define MROWS 4            // base rows per VD item (stride 3)
#define NGRP 66            // 22 * 3 row-groups
#define VDN (NGRP*NC*BB)   // 1056 VD items (heavy-first: y0 ascending)
#define HN  (HH*BB)        // 512 H items (light, last)
#define TOT (VDN+HN)       // 1568 work items
#define GRID 592           // 4 blocks/SM * 148 SMs, all co-resident
#define DIV1 39518208.0f   // 603 * 65536

// per-batch accumulators: [0]=S1 (|dG|*Rat), [1]=S2 (|dG|*(Rat>0)),
// [2]=pos_cnt, [3]=S4 (|dP|), [4]=T1, [5]=roi_sum
__device__ double g_acc[BB][6];
__device__ unsigned bar_ctr;             // zero-init
__device__ volatile unsigned bar_gen;    // zero-init
__device__ unsigned q_ctr[2];            // work queues, zero-init; reset in finalize

struct Smem {
    float4 s4[2][WW];   // {P0,P1,P2,G0}
    float2 s2[2][WW];   // {G1,G2}
    float  sr[2][WW];   // roi
    float  red[8];
    int    item;
};

__device__ __forceinline__ float warpsum(float v) {
#pragma unroll
    for (int o = 16; o; o >>= 1) v += __shfl_xor_sync(0xffffffffu, v, o);
    return v;
}

__device__ __forceinline__ void grid_barrier() {
    __syncthreads();
    if (threadIdx.x == 0) {
        __threadfence();
        unsigned gen = bar_gen;
        if (atomicAdd(&bar_ctr, 1) == GRID - 1) {
            bar_ctr = 0;
            __threadfence();
            bar_gen = gen + 1;
        } else {
            while (bar_gen == gen) __nanosleep(64);
        }
        __threadfence();
    }
    __syncthreads();
}

// PASS 0 accumulators: a0=S1, a1=S2, a2=pos, a3=S4, a4=roi_sum. PASS 1: a0=T1.
template<int PASS>
__device__ __forceinline__ void do_item(int id,
                                        const float* __restrict__ Pred,
                                        const float* __restrict__ GT,
                                        const float* __restrict__ ROI,
                                        Smem* sm, float ic0, float ic1) {
    const int x = threadIdx.x;
    float a0 = 0.f, a1 = 0.f, a2 = 0.f, a3 = 0.f, a4 = 0.f;
    int b;

    // P: bool (roi pair active). unmasked math, predicated accumulation
    // (exact: roi in {0,1}).
#define ACCUM(PP, tt, uu)                                         \
    do {                                                          \
        if (PASS == 0) {                                          \
            float t_ = (tt), u_ = (uu);                           \
            float q = __fdividef(t_ * fabsf(u_), u_ + 1e-5f);     \
            if ((PP) && q  > 0.0f) { a0 += q; a1 += fabsf(u_); }  \
            if ((PP) && u_ > 0.0f) a2 += 1.0f;                    \
            if (PP) a3 += fabsf(t_);                              \
        } else {                                                  \
            float e = (uu) - (tt) * ic;                           \
            if (PP) a0 += fabsf(e);                               \
        }                                                         \
    } while (0)

    if (id < VDN) {
        // ---- VD item: 4 base rows (stride 3), stream rows y0+1+3j ----
        const int cpos = id % NC;
        const int g    = (id / NC) % NGRP;
        b              = id / (NC * NGRP);
        const int y0   = 12 * (g / 3) + (g % 3);
        const float ic = (PASS == 1) ? (b ? ic1 : ic0) : 0.f;

        const float* Pb = Pred + b * LL * PLANE;
        const float* Gb = GT   + b * LL * PLANE;
        const float* Rb = ROI  + b * PLANE;

        float bp[MROWS][LL], bg[MROWS][LL];
        bool  Pbase[MROWS];
#pragma unroll
        for (int i = 0; i < MROWS; ++i) {
            int yr = y0 + 3 * i;
            int off = min(yr, HH - 1) * WW + x;
            Pbase[i] = (yr < HH) && (Rb[off] > 0.0f);
#pragma unroll
            for (int l = 0; l < LL; ++l) {
                bp[i][l] = Pb[l * PLANE + off];
                bg[i][l] = Gb[l * PLANE + off];
            }
        }

        const int jmax = min((HH - 2 - y0) / 3, NSCALE + MROWS - 2);
        int p = 0;
        for (int j = cpos; j <= jmax; j += NC) {
            const int Roff = (y0 + 1 + 3 * j) * WW + x;
            float vr  = Rb[Roff];
            float vp0 = Pb[Roff], vp1 = Pb[PLANE + Roff], vp2 = Pb[2 * PLANE + Roff];
            float vg0 = Gb[Roff], vg1 = Gb[PLANE + Roff], vg2 = Gb[2 * PLANE + Roff];
            sm->s4[p][x] = make_float4(vp0, vp1, vp2, vg0);
            sm->s2[p][x] = make_float2(vg1, vg2);
            sm->sr[p][x] = vr;
            __syncthreads();
            const bool Pv = vr > 0.0f;
#pragma unroll
            for (int i = 0; i < MROWS; ++i) {
                if (i <= j && j - i < NSCALE) {
                    // vertical: all registers
                    bool PV = Pbase[i] && Pv;
                    ACCUM(PV, bp[i][0] - vp0, bg[i][0] - vg0);
                    ACCUM(PV, bp[i][1] - vp1, bg[i][1] - vg1);
                    ACCUM(PV, bp[i][2] - vp2, bg[i][2] - vg2);
                    // diagonal: packed smem at x+s
                    int xs = x + 3 * (j - i) + 1;
                    if (xs < WW) {
                        float4 A  = sm->s4[p][xs];
                        float2 B2 = sm->s2[p][xs];
                        bool PD = Pbase[i] && (sm->sr[p][xs] > 0.0f);
                        ACCUM(PD, bp[i][0] - A.x, bg[i][0] - A.w);
                        ACCUM(PD, bp[i][1] - A.y, bg[i][1] - B2.x);
                        ACCUM(PD, bp[i][2] - A.z, bg[i][2] - B2.y);
                    }
                }
            }
            p ^= 1;
        }
    } else {
        // ---- H item: one base row, all 67 horizontal scales ----
        const int hid = id - VDN;
        b = hid & 1;
        const int y = hid >> 1;
        const float ic = (PASS == 1) ? (b ? ic1 : ic0) : 0.f;

        const float* Pb = Pred + b * LL * PLANE;
        const float* Gb = GT   + b * LL * PLANE;
        const float* Rb = ROI  + b * PLANE;

        const int off = y * WW + x;
        float br0 = Rb[off];
        const bool Pb0 = br0 > 0.0f;
        float hp[LL], hg[LL];
#pragma unroll
        for (int l = 0; l < LL; ++l) {
            hp[l] = Pb[l * PLANE + off];
            hg[l] = Gb[l * PLANE + off];
        }
        sm->s4[0][x] = make_float4(hp[0], hp[1], hp[2], hg[0]);
        sm->s2[0][x] = make_float2(hg[1], hg[2]);
        sm->sr[0][x] = br0;
        if (PASS == 0) a4 = br0;     // roi_sum, once per (b,y)
        __syncthreads();

        for (int k = 0; k < NSCALE; ++k) {
            int xs = x + 1 + 3 * k;
            if (xs < WW) {
                float4 A  = sm->s4[0][xs];
                float2 B2 = sm->s2[0][xs];
                bool PH = Pb0 && (sm->sr[0][xs] > 0.0f);
                ACCUM(PH, hp[0] - A.x, hg[0] - A.w);
                ACCUM(PH, hp[1] - A.y, hg[1] - B2.x);
                ACCUM(PH, hp[2] - A.z, hg[2] - B2.y);
            }
        }
    }
#undef ACCUM

    // ---- block reduction -> double atomics ----
    const int lane = threadIdx.x & 31, wid = threadIdx.x >> 5;
    const int nsum = (PASS == 0) ? 5 : 1;
    float vals[5] = {a0, a1, a2, a3, a4};
    const int slot[5] = {(PASS == 0) ? 0 : 4, 1, 2, 3, 5};
#pragma unroll
    for (int i = 0; i < 5; ++i) {
        if (i >= nsum) break;
        float v = warpsum(vals[i]);
        __syncthreads();
        if (lane == 0) sm->red[wid] = v;
        __syncthreads();
        if (wid == 0) {
            float w = (lane < 8) ? sm->red[lane] : 0.0f;
            w = warpsum(w);
            if (lane == 0 && w != 0.0f) atomicAdd(&g_acc[b][slot[i]], (double)w);
        }
    }
    __syncthreads();   // smem safe for next item
}

__global__ void __launch_bounds__(256, 4)
k_fused(const float* __restrict__ Pred, const float* __restrict__ GT,
        const float* __restrict__ ROI, float* out, int out_size) {
    __shared__ Smem sm;

    // ---- pass 0: dynamic work queue (items ordered heavy-first) ----
    for (;;) {
        if (threadIdx.x == 0) sm.item = (int)atomicAdd(&q_ctr[0], 1u);
        __syncthreads();
        int it = sm.item;
        if (it >= TOT) break;
        do_item<0>(it, Pred, GT, ROI, &sm, 0.f, 0.f);
    }

    grid_barrier();

    // ---- NormConst (every thread, from 4 global doubles) ----
    float ic[BB];
#pragma unroll
    for (int bb = 0; bb < BB; ++bb) {
        float S1 = (float)g_acc[bb][0], S2 = (float)g_acc[bb][1];
        float c = S1 / (S2 + 1e-4f);
        ic[bb] = (c > 1e-4f) ? (1.0f / c) : 1.0f;
    }

    // ---- pass 1: dynamic work queue ----
    for (;;) {
        if (threadIdx.x == 0) sm.item = (int)atomicAdd(&q_ctr[1], 1u);
        __syncthreads();
        int it = sm.item;
        if (it >= TOT) break;
        do_item<1>(it, Pred, GT, ROI, &sm, ic[0], ic[1]);
    }

    grid_barrier();

    // ---- finalize (block 0) ----
    if (blockIdx.x == 0 && threadIdx.x == 0) {
        float loss = 0.f;
        float cs[BB];
#pragma unroll
        for (int bb = 0; bb < BB; ++bb) {
            float S1 = (float)g_acc[bb][0], S2 = (float)g_acc[bb][1];
            float c = S1 / (S2 + 1e-4f);
            cs[bb] = c;
            float term1 = (c > 1e-4f) ? ((float)g_acc[bb][4] / DIV1) : 0.0f;
            float roi_sum  = (float)g_acc[bb][5];
            float pos      = (float)g_acc[bb][2];
            float mean_prd = (float)g_acc[bb][3] / pos;
            bool big = roi_sum > 200.0f;
            float term2 = (big && mean_prd > 30.0f && c > 10.0f) ? (mean_prd - 30.0f) : 0.0f;
            float fact = 0.1f / (c + 0.001f);
            float term3 = (big && mean_prd < 2.0f && c < 0.1f) ? ((0.2f - mean_prd) * fact) : 0.0f;
            loss += term1 + term2 + term3;
        }
        if (out_size >= 1) out[0] = loss;
        if (out_size >= 3) { out[1] = cs[0]; out[2] = cs[1]; }
        // reset state for the next graph replay (statics start zeroed)
#pragma unroll
        for (int i = 0; i < BB * 6; ++i) ((double*)g_acc)[i] = 0.0;
        q_ctr[0] = 0;
        q_ctr[1] = 0;
    }
}

extern "C" void kernel_launch(void* const* d_in, const int* in_sizes, int n_in,
                              void* d_out, int out_size) {
    const float* Pred = (const float*)d_in[0];
    const float* GT   = (const float*)d_in[1];
    const float* ROI  = (const float*)d_in[2];
    float* out = (float*)d_out;

    k_fused<<<GRID, 256>>>(Pred, GT, ROI, out, out_size);
}